// round 2
// baseline (speedup 1.0000x reference)
#include <cuda_runtime.h>
#include <cuda_bf16.h>
#include <cstdint>

// Problem constants
#define NN      50000
#define EE      800000
#define IND     128
#define HIDD    256
#define CAP     96      // max in-degree bucket capacity (Poisson(16), max deg ~45)

// Scratch (device globals; allocation-free)
__device__ int   g_is64;
__device__ int   g_cnt[NN];
__device__ int   g_elist[(size_t)NN * CAP];       // src lists bucketed by dst
__device__ float g_u[(size_t)NN * IND];           // (1+eps1)*x + agg1
__device__ float g_y[(size_t)NN * 2];             // h1 @ W2 per node

// ---------------------------------------------------------------------------
// K0: zero counts + detect int64 vs int32 edge_index
// ---------------------------------------------------------------------------
__global__ void k_init(const int* __restrict__ ei, int nNodes) {
    int i = blockIdx.x * blockDim.x + threadIdx.x;
    if (i < nNodes) g_cnt[i] = 0;
    if (blockIdx.x == 0 && threadIdx.x < 32) {
        // If data is int64 (values are node ids < 2^31), every odd 32-bit
        // word of the first 32 entries is 0.
        int w = ei[2 * threadIdx.x + 1];
        unsigned nz = __ballot_sync(0xffffffffu, w != 0);
        if (threadIdx.x == 0) g_is64 = (nz == 0u) ? 1 : 0;
    }
}

// ---------------------------------------------------------------------------
// K1: build per-dst adjacency buckets (int atomics only)
// ---------------------------------------------------------------------------
__global__ void k_build(const int* __restrict__ ei, int E) {
    int e = blockIdx.x * blockDim.x + threadIdx.x;
    if (e >= E) return;
    int src, dst;
    if (g_is64) { src = ei[2 * e]; dst = ei[2 * (E + e)]; }
    else        { src = ei[e];     dst = ei[E + e]; }
    int p = atomicAdd(&g_cnt[dst], 1);
    if (p < CAP) g_elist[(size_t)dst * CAP + p] = src;
}

// ---------------------------------------------------------------------------
// K2: layer-1 aggregation (gather): u[n] = (1+eps1)*x[n] + sum_{src->n} x[src]
// warp per node, one float4 per lane (128 floats/row = 32 float4)
// ---------------------------------------------------------------------------
__global__ void __launch_bounds__(256) k_agg1(const float* __restrict__ x,
                                              const float* __restrict__ eps1p,
                                              int nNodes) {
    int warp = (blockIdx.x * blockDim.x + threadIdx.x) >> 5;
    int lane = threadIdx.x & 31;
    if (warp >= nNodes) return;
    const float4* __restrict__ xv = (const float4*)x;
    float s1 = 1.0f + *eps1p;
    float4 a = xv[(size_t)warp * 32 + lane];
    float4 acc;
    acc.x = s1 * a.x; acc.y = s1 * a.y; acc.z = s1 * a.z; acc.w = s1 * a.w;

    int deg = g_cnt[warp]; if (deg > CAP) deg = CAP;
    const int* __restrict__ lst = &g_elist[(size_t)warp * CAP];
    int e = 0;
    for (; e + 4 <= deg; e += 4) {
        int i0 = lst[e], i1 = lst[e + 1], i2 = lst[e + 2], i3 = lst[e + 3];
        float4 v0 = xv[(size_t)i0 * 32 + lane];
        float4 v1 = xv[(size_t)i1 * 32 + lane];
        float4 v2 = xv[(size_t)i2 * 32 + lane];
        float4 v3 = xv[(size_t)i3 * 32 + lane];
        acc.x += v0.x + v1.x + v2.x + v3.x;
        acc.y += v0.y + v1.y + v2.y + v3.y;
        acc.z += v0.z + v1.z + v2.z + v3.z;
        acc.w += v0.w + v1.w + v2.w + v3.w;
    }
    for (; e < deg; e++) {
        float4 v = xv[(size_t)lst[e] * 32 + lane];
        acc.x += v.x; acc.y += v.y; acc.z += v.z; acc.w += v.w;
    }
    ((float4*)g_u)[(size_t)warp * 32 + lane] = acc;
}

// ---------------------------------------------------------------------------
// K3: fused GEMM1 (u @ W1 + b1, ReLU) + projection y = h @ W2
//     + out init = (1+eps2)*y + b2.   h1 is never materialized.
// BM=64 rows/CTA, BN=256 (full hidden), K=128 in 4 chunks of BK=32.
// 256 threads, each owns a 4x16 fragment. Packed f32x2 FMA (2x fp32 rate).
// Static shared memory only (≈44.5 KB < 48 KB) — no attribute opt-in needed.
// ---------------------------------------------------------------------------
#define BK 32

__global__ void __launch_bounds__(256, 2) k_gemm(
    const float* __restrict__ W1, const float* __restrict__ b1,
    const float* __restrict__ W2, const float* __restrict__ b2,
    const float* __restrict__ eps2p, float* __restrict__ outp, int nNodes) {

    __shared__ float As[BK][68];     // transposed u chunk: As[k][m]
    __shared__ float Bs[BK][256];    // W1 chunk [k][n]
    __shared__ float Ws[512];        // W2 [256][2]
    __shared__ float B1s[256];       // b1

    int t = threadIdx.x;
    int rowBase = blockIdx.x * 64;

    for (int i = t; i < 512; i += 256) Ws[i] = W2[i];
    B1s[t] = b1[t];

    int r0 = (t >> 4) * 4;     // row offset within tile: 0..60
    int c0 = (t & 15) * 16;    // col offset: 0..240

    unsigned long long acc[4][8];
    #pragma unroll
    for (int r = 0; r < 4; r++)
        #pragma unroll
        for (int j = 0; j < 8; j++) acc[r][j] = 0ull;

    const float4* __restrict__ uv  = (const float4*)g_u;
    const float4* __restrict__ W1v = (const float4*)W1;

    for (int kc = 0; kc < 4; kc++) {
        __syncthreads();
        // Load u chunk (64 rows x 32 k) transposed into As[k][m]
        #pragma unroll
        for (int i = t; i < 512; i += 256) {
            int m  = i >> 3;           // 0..63
            int k4 = i & 7;            // float4 index within chunk
            int gr = rowBase + m;
            float4 v = make_float4(0.f, 0.f, 0.f, 0.f);
            if (gr < nNodes) v = uv[(size_t)gr * 32 + kc * 8 + k4];
            int kb = k4 * 4;
            As[kb + 0][m] = v.x;
            As[kb + 1][m] = v.y;
            As[kb + 2][m] = v.z;
            As[kb + 3][m] = v.w;
        }
        // Load W1 chunk (32 rows x 256 cols = 2048 float4)
        #pragma unroll
        for (int i = t; i < 2048; i += 256)
            ((float4*)Bs)[i] = W1v[kc * 2048 + i];
        __syncthreads();

        #pragma unroll
        for (int k = 0; k < BK; k++) {
            float4 a4 = *(const float4*)&As[k][r0];
            const unsigned long long* bp = (const unsigned long long*)&Bs[k][c0];
            unsigned long long b[8];
            #pragma unroll
            for (int j = 0; j < 8; j++) b[j] = bp[j];
            float ar[4] = {a4.x, a4.y, a4.z, a4.w};
            #pragma unroll
            for (int r = 0; r < 4; r++) {
                unsigned long long aa;
                asm("mov.b64 %0, {%1, %1};" : "=l"(aa) : "f"(ar[r]));
                #pragma unroll
                for (int j = 0; j < 8; j++)
                    asm("fma.rn.f32x2 %0, %1, %2, %0;"
                        : "+l"(acc[r][j]) : "l"(aa), "l"(b[j]));
            }
        }
    }

    // Epilogue: bias + ReLU + project to 2-dim y; reduce across 16 threads/row
    float py0[4] = {0.f, 0.f, 0.f, 0.f};
    float py1[4] = {0.f, 0.f, 0.f, 0.f};
    #pragma unroll
    for (int r = 0; r < 4; r++) {
        #pragma unroll
        for (int j = 0; j < 8; j++) {
            float lo, hi;
            asm("mov.b64 {%0, %1}, %2;" : "=f"(lo), "=f"(hi) : "l"(acc[r][j]));
            int col = c0 + 2 * j;
            lo = fmaxf(lo + B1s[col], 0.f);
            hi = fmaxf(hi + B1s[col + 1], 0.f);
            py0[r] += lo * Ws[col * 2 + 0] + hi * Ws[(col + 1) * 2 + 0];
            py1[r] += lo * Ws[col * 2 + 1] + hi * Ws[(col + 1) * 2 + 1];
        }
    }
    #pragma unroll
    for (int off = 8; off >= 1; off >>= 1) {
        #pragma unroll
        for (int r = 0; r < 4; r++) {
            py0[r] += __shfl_down_sync(0xffffffffu, py0[r], off, 16);
            py1[r] += __shfl_down_sync(0xffffffffu, py1[r], off, 16);
        }
    }
    if ((t & 15) == 0) {
        float e2 = 1.0f + *eps2p;
        float bb0 = b2[0], bb1 = b2[1];
        #pragma unroll
        for (int r = 0; r < 4; r++) {
            int row = rowBase + r0 + r;
            if (row < nNodes) {
                float y0 = py0[r], y1 = py1[r];
                g_y[2 * row]     = y0;
                g_y[2 * row + 1] = y1;
                outp[2 * row]     = fmaf(e2, y0, bb0);
                outp[2 * row + 1] = fmaf(e2, y1, bb1);
            }
        }
    }
}

// ---------------------------------------------------------------------------
// K4: layer-2 aggregation in 2-dim space: out[n] += sum_{src->n} y[src]
// ---------------------------------------------------------------------------
__global__ void __launch_bounds__(256) k_agg2(float* __restrict__ outp, int nNodes) {
    int n = blockIdx.x * blockDim.x + threadIdx.x;
    if (n >= nNodes) return;
    int deg = g_cnt[n]; if (deg > CAP) deg = CAP;
    const int* __restrict__ lst = &g_elist[(size_t)n * CAP];
    const float2* __restrict__ yv = (const float2*)g_y;
    float a0 = 0.f, a1 = 0.f;
    int e = 0;
    for (; e + 4 <= deg; e += 4) {
        int i0 = lst[e], i1 = lst[e + 1], i2 = lst[e + 2], i3 = lst[e + 3];
        float2 v0 = yv[i0], v1 = yv[i1], v2 = yv[i2], v3 = yv[i3];
        a0 += v0.x + v1.x + v2.x + v3.x;
        a1 += v0.y + v1.y + v2.y + v3.y;
    }
    for (; e < deg; e++) {
        float2 v = yv[lst[e]];
        a0 += v.x; a1 += v.y;
    }
    float2* o = (float2*)outp;
    float2 cur = o[n];
    cur.x += a0; cur.y += a1;
    o[n] = cur;
}

// ---------------------------------------------------------------------------
extern "C" void kernel_launch(void* const* d_in, const int* in_sizes, int n_in,
                              void* d_out, int out_size) {
    const float* x     = (const float*)d_in[0];
    const int*   ei    = (const int*)d_in[1];   // int32 or int64 words (detected)
    const float* W1    = (const float*)d_in[2];
    const float* b1    = (const float*)d_in[3];
    const float* W2    = (const float*)d_in[4];
    const float* b2    = (const float*)d_in[5];
    const float* eps1p = (const float*)d_in[6];
    const float* eps2p = (const float*)d_in[7];
    float* outp = (float*)d_out;

    int nNodes = in_sizes[0] / IND;          // 50000
    int E      = in_sizes[1] / 2;            // 800000 edges

    k_init<<<(nNodes + 255) / 256, 256>>>(ei, nNodes);
    k_build<<<(E + 255) / 256, 256>>>(ei, E);
    k_agg1<<<(nNodes + 7) / 8, 256>>>(x, eps1p, nNodes);
    k_gemm<<<(nNodes + 63) / 64, 256>>>(W1, b1, W2, b2, eps2p, outp, nNodes);
    k_agg2<<<(nNodes + 255) / 256, 256>>>(outp, nNodes);
}

// round 3
// speedup vs baseline: 2.1233x; 2.1233x over previous
#include <cuda_runtime.h>
#include <cuda_bf16.h>
#include <cstdint>

// Problem constants
#define NN      50000
#define EE      800000
#define IND     128
#define HIDD    256
#define CAP     96      // max in-degree bucket capacity (Poisson(16), max deg ~45)

// Scratch (device globals; allocation-free)
__device__ int   g_is64;
__device__ int   g_cnt[NN];
__device__ int   g_elist[(size_t)NN * CAP];       // src lists bucketed by dst
__device__ float g_u[(size_t)NN * IND];           // (1+eps1)*x + agg1
__device__ float g_y[(size_t)NN * 2];             // h1 @ W2 per node (atomic-accum)

// ---------------------------------------------------------------------------
// K0: zero counts + zero y + detect int64 vs int32 edge_index
// ---------------------------------------------------------------------------
__global__ void k_init(const int* __restrict__ ei, int nNodes) {
    int i = blockIdx.x * blockDim.x + threadIdx.x;
    if (i < nNodes) {
        g_cnt[i] = 0;
        g_y[2 * i]     = 0.f;
        g_y[2 * i + 1] = 0.f;
    }
    if (blockIdx.x == 0 && threadIdx.x < 32) {
        // If data is int64 (node ids < 2^31), every odd 32-bit word is 0.
        int w = ei[2 * threadIdx.x + 1];
        unsigned nz = __ballot_sync(0xffffffffu, w != 0);
        if (threadIdx.x == 0) g_is64 = (nz == 0u) ? 1 : 0;
    }
}

// ---------------------------------------------------------------------------
// K1: build per-dst adjacency buckets (int atomics only)
// ---------------------------------------------------------------------------
__global__ void k_build(const int* __restrict__ ei, int E) {
    int e = blockIdx.x * blockDim.x + threadIdx.x;
    if (e >= E) return;
    int src, dst;
    if (g_is64) { src = ei[2 * e]; dst = ei[2 * (E + e)]; }
    else        { src = ei[e];     dst = ei[E + e]; }
    int p = atomicAdd(&g_cnt[dst], 1);
    if (p < CAP) g_elist[(size_t)dst * CAP + p] = src;
}

// ---------------------------------------------------------------------------
// K2: layer-1 aggregation (gather): u[n] = (1+eps1)*x[n] + sum_{src->n} x[src]
// warp per node, one float4 per lane (128 floats/row = 32 float4)
// ---------------------------------------------------------------------------
__global__ void __launch_bounds__(256) k_agg1(const float* __restrict__ x,
                                              const float* __restrict__ eps1p,
                                              int nNodes) {
    int warp = (blockIdx.x * blockDim.x + threadIdx.x) >> 5;
    int lane = threadIdx.x & 31;
    if (warp >= nNodes) return;
    const float4* __restrict__ xv = (const float4*)x;
    float s1 = 1.0f + *eps1p;
    float4 a = xv[(size_t)warp * 32 + lane];
    float4 acc;
    acc.x = s1 * a.x; acc.y = s1 * a.y; acc.z = s1 * a.z; acc.w = s1 * a.w;

    int deg = g_cnt[warp]; if (deg > CAP) deg = CAP;
    const int* __restrict__ lst = &g_elist[(size_t)warp * CAP];
    int e = 0;
    for (; e + 4 <= deg; e += 4) {
        int i0 = lst[e], i1 = lst[e + 1], i2 = lst[e + 2], i3 = lst[e + 3];
        float4 v0 = xv[(size_t)i0 * 32 + lane];
        float4 v1 = xv[(size_t)i1 * 32 + lane];
        float4 v2 = xv[(size_t)i2 * 32 + lane];
        float4 v3 = xv[(size_t)i3 * 32 + lane];
        acc.x += v0.x + v1.x + v2.x + v3.x;
        acc.y += v0.y + v1.y + v2.y + v3.y;
        acc.z += v0.z + v1.z + v2.z + v3.z;
        acc.w += v0.w + v1.w + v2.w + v3.w;
    }
    for (; e < deg; e++) {
        float4 v = xv[(size_t)lst[e] * 32 + lane];
        acc.x += v.x; acc.y += v.y; acc.z += v.z; acc.w += v.w;
    }
    ((float4*)g_u)[(size_t)warp * 32 + lane] = acc;
}

// ---------------------------------------------------------------------------
// K3: fused GEMM1 (u @ W1 + b1, ReLU) + projection partial y += h @ W2[tile]
// BM=128 x BN=128 tile, grid (391, 2). 256 threads, 8x8 fragment per thread
// laid out as 2x2 float4 sub-tiles (conflict-free smem reads).
// Packed f32x2 FMA for 2x fp32 throughput. h1 never materialized.
// ---------------------------------------------------------------------------
#define BM 128
#define BN 128
#define BK 32
#define AST 132   // As row stride in floats (128 + 4 pad)

__global__ void __launch_bounds__(256, 2) k_gemm(
    const float* __restrict__ W1, const float* __restrict__ b1,
    const float* __restrict__ W2, const float* __restrict__ b2,
    int nNodes) {

    __shared__ float As[BK][AST];    // transposed u chunk [k][m]
    __shared__ float Bs[BK][BN];     // W1 chunk [k][n_local]
    __shared__ float Ws[BN * 2];     // W2 slice for this col tile
    __shared__ float B1s[BN];        // b1 slice

    int t = threadIdx.x;
    int rowBase = blockIdx.x * BM;
    int colBase = blockIdx.y * BN;   // 0 or 128

    // Epilogue params for this column tile
    if (t < 256) Ws[t] = W2[colBase * 2 + t];   // W2 is row-major [256][2]
    if (t < BN)  B1s[t] = b1[colBase + t];

    int tx = t & 15;         // 16 col groups
    int ty = t >> 4;         // 16 row groups

    unsigned long long acc[8][4];
    #pragma unroll
    for (int r = 0; r < 8; r++)
        #pragma unroll
        for (int j = 0; j < 4; j++) acc[r][j] = 0ull;

    const float4* __restrict__ uv  = (const float4*)g_u;
    const float4* __restrict__ W1v = (const float4*)W1;

    for (int kc = 0; kc < 4; kc++) {
        __syncthreads();
        // Load u chunk (128 rows x 32 k), transpose into As[k][m]
        #pragma unroll
        for (int i = t; i < 1024; i += 256) {
            int m  = i >> 3;            // 0..127
            int k4 = i & 7;             // float4 index within 32-k chunk
            int gr = rowBase + m;
            float4 v = make_float4(0.f, 0.f, 0.f, 0.f);
            if (gr < nNodes) v = uv[(size_t)gr * 32 + kc * 8 + k4];
            int kb = k4 * 4;
            As[kb + 0][m] = v.x;
            As[kb + 1][m] = v.y;
            As[kb + 2][m] = v.z;
            As[kb + 3][m] = v.w;
        }
        // Load W1 chunk: rows kc*32..+31, cols colBase..+127 (32x32 float4)
        #pragma unroll
        for (int i = t; i < 1024; i += 256) {
            int kk = i >> 5;            // 0..31
            int c4 = i & 31;            // 0..31 float4s per row
            ((float4*)&Bs[kk][0])[c4] =
                W1v[(size_t)(kc * 32 + kk) * 64 + (colBase >> 2) + c4];
        }
        __syncthreads();

        #pragma unroll 8
        for (int k = 0; k < BK; k++) {
            float4 a0 = *(const float4*)&As[k][ty * 4];
            float4 a1 = *(const float4*)&As[k][ty * 4 + 64];
            float4 b0 = *(const float4*)&Bs[k][tx * 4];
            float4 b1f = *(const float4*)&Bs[k][tx * 4 + 64];
            unsigned long long bb[4];
            asm("mov.b64 %0, {%1, %2};" : "=l"(bb[0]) : "f"(b0.x), "f"(b0.y));
            asm("mov.b64 %0, {%1, %2};" : "=l"(bb[1]) : "f"(b0.z), "f"(b0.w));
            asm("mov.b64 %0, {%1, %2};" : "=l"(bb[2]) : "f"(b1f.x), "f"(b1f.y));
            asm("mov.b64 %0, {%1, %2};" : "=l"(bb[3]) : "f"(b1f.z), "f"(b1f.w));
            float ar[8] = {a0.x, a0.y, a0.z, a0.w, a1.x, a1.y, a1.z, a1.w};
            #pragma unroll
            for (int r = 0; r < 8; r++) {
                unsigned long long aa;
                asm("mov.b64 %0, {%1, %1};" : "=l"(aa) : "f"(ar[r]));
                #pragma unroll
                for (int j = 0; j < 4; j++)
                    asm("fma.rn.f32x2 %0, %1, %2, %0;"
                        : "+l"(acc[r][j]) : "l"(aa), "l"(bb[j]));
            }
        }
    }

    // Epilogue: bias + ReLU + project this 128-col slice onto W2 -> partial y
    float py0[8], py1[8];
    #pragma unroll
    for (int r = 0; r < 8; r++) { py0[r] = 0.f; py1[r] = 0.f; }
    #pragma unroll
    for (int r = 0; r < 8; r++) {
        #pragma unroll
        for (int j = 0; j < 4; j++) {
            float lo, hi;
            asm("mov.b64 {%0, %1}, %2;" : "=f"(lo), "=f"(hi) : "l"(acc[r][j]));
            int cl = tx * 4 + (j & 1) * 2 + (j >> 1) * 64;   // local col of lo
            lo = fmaxf(lo + B1s[cl], 0.f);
            hi = fmaxf(hi + B1s[cl + 1], 0.f);
            py0[r] += lo * Ws[cl * 2 + 0] + hi * Ws[cl * 2 + 2];
            py1[r] += lo * Ws[cl * 2 + 1] + hi * Ws[cl * 2 + 3];
        }
    }
    // Reduce across the 16 tx-threads sharing each row (half-warp shuffles)
    #pragma unroll
    for (int off = 8; off >= 1; off >>= 1) {
        #pragma unroll
        for (int r = 0; r < 8; r++) {
            py0[r] += __shfl_down_sync(0xffffffffu, py0[r], off, 16);
            py1[r] += __shfl_down_sync(0xffffffffu, py1[r], off, 16);
        }
    }
    if (tx == 0) {
        #pragma unroll
        for (int r = 0; r < 8; r++) {
            int row = rowBase + ty * 4 + (r & 3) + ((r >> 2) * 64);
            if (row < nNodes) {
                // exactly 2 commutative adds per element (by=0, by=1):
                // bitwise deterministic
                atomicAdd(&g_y[2 * row],     py0[r]);
                atomicAdd(&g_y[2 * row + 1], py1[r]);
            }
        }
    }
}

// ---------------------------------------------------------------------------
// K4: layer-2: out[n] = (1+eps2)*y[n] + b2 + sum_{src->n} y[src]
// ---------------------------------------------------------------------------
__global__ void __launch_bounds__(256) k_agg2(const float* __restrict__ b2,
                                              const float* __restrict__ eps2p,
                                              float* __restrict__ outp,
                                              int nNodes) {
    int n = blockIdx.x * blockDim.x + threadIdx.x;
    if (n >= nNodes) return;
    int deg = g_cnt[n]; if (deg > CAP) deg = CAP;
    const int* __restrict__ lst = &g_elist[(size_t)n * CAP];
    const float2* __restrict__ yv = (const float2*)g_y;
    float a0 = 0.f, a1 = 0.f;
    int e = 0;
    for (; e + 4 <= deg; e += 4) {
        int i0 = lst[e], i1 = lst[e + 1], i2 = lst[e + 2], i3 = lst[e + 3];
        float2 v0 = yv[i0], v1 = yv[i1], v2 = yv[i2], v3 = yv[i3];
        a0 += v0.x + v1.x + v2.x + v3.x;
        a1 += v0.y + v1.y + v2.y + v3.y;
    }
    for (; e < deg; e++) {
        float2 v = yv[lst[e]];
        a0 += v.x; a1 += v.y;
    }
    float e2 = 1.0f + *eps2p;
    float2 yn = yv[n];
    float2 res;
    res.x = fmaf(e2, yn.x, b2[0]) + a0;
    res.y = fmaf(e2, yn.y, b2[1]) + a1;
    ((float2*)outp)[n] = res;
}

// ---------------------------------------------------------------------------
extern "C" void kernel_launch(void* const* d_in, const int* in_sizes, int n_in,
                              void* d_out, int out_size) {
    const float* x     = (const float*)d_in[0];
    const int*   ei    = (const int*)d_in[1];   // int32 or int64 words (detected)
    const float* W1    = (const float*)d_in[2];
    const float* b1    = (const float*)d_in[3];
    const float* W2    = (const float*)d_in[4];
    const float* b2    = (const float*)d_in[5];
    const float* eps1p = (const float*)d_in[6];
    const float* eps2p = (const float*)d_in[7];
    float* outp = (float*)d_out;

    int nNodes = in_sizes[0] / IND;          // 50000
    int E      = in_sizes[1] / 2;            // 800000 edges

    k_init<<<(nNodes + 255) / 256, 256>>>(ei, nNodes);
    k_build<<<(E + 255) / 256, 256>>>(ei, E);
    k_agg1<<<(nNodes + 7) / 8, 256>>>(x, eps1p, nNodes);
    dim3 ggrid((nNodes + BM - 1) / BM, 2);
    k_gemm<<<ggrid, 256>>>(W1, b1, W2, b2, nNodes);
    k_agg2<<<(nNodes + 255) / 256, 256>>>(b2, eps2p, outp, nNodes);
}

// round 5
// speedup vs baseline: 2.1574x; 1.0160x over previous
#include <cuda_runtime.h>
#include <cuda_bf16.h>
#include <cstdint>

// Problem constants
#define NN      50000
#define IND     128
#define HIDD    256
#define CAP     96      // max in-degree bucket capacity (Poisson(16), max deg ~45)

// Scratch (device globals; allocation-free)
__device__ int   g_is64;
__device__ int   g_cnt[NN];
__device__ int   g_elist[(size_t)NN * CAP];        // src lists bucketed by dst
// u in bf16, fragment-permuted: per node 64 words; within each 16-k group the
// 8 words are ordered [w0,w4,w1,w5,w2,w6,w3,w7] so an mma A-fragment pair
// {a0,a2} (and {a1,a3}) is one aligned 8-byte load.
__device__ unsigned int g_uhi[(size_t)NN * 64];
__device__ unsigned int g_ulo[(size_t)NN * 64];
// W1 split, [n][k] bf16 with the same per-16k permutation: {b0,b1} = one LDG.64
__device__ unsigned int g_Bhi[256 * 64];
__device__ unsigned int g_Blo[256 * 64];
__device__ float g_y[(size_t)NN * 2];              // h1 @ W2 per node

__device__ __forceinline__ unsigned pack_bf16(float lo, float hi) {
    unsigned short a = __bfloat16_as_ushort(__float2bfloat16_rn(lo));
    unsigned short b = __bfloat16_as_ushort(__float2bfloat16_rn(hi));
    return ((unsigned)b << 16) | (unsigned)a;
}

// ---------------------------------------------------------------------------
// K0: zero counts + detect int64 vs int32 edge_index
// ---------------------------------------------------------------------------
__global__ void k_init(const int* __restrict__ ei, int nNodes) {
    int i = blockIdx.x * blockDim.x + threadIdx.x;
    if (i < nNodes) g_cnt[i] = 0;
    if (blockIdx.x == 0 && threadIdx.x < 32) {
        int w = ei[2 * threadIdx.x + 1];
        unsigned nz = __ballot_sync(0xffffffffu, w != 0);
        if (threadIdx.x == 0) g_is64 = (nz == 0u) ? 1 : 0;
    }
}

// ---------------------------------------------------------------------------
// K1: build per-dst adjacency buckets (int atomics only)
// ---------------------------------------------------------------------------
__global__ void k_build(const int* __restrict__ ei, int E) {
    int e = blockIdx.x * blockDim.x + threadIdx.x;
    if (e >= E) return;
    int src, dst;
    if (g_is64) { src = ei[2 * e]; dst = ei[2 * (E + e)]; }
    else        { src = ei[e];     dst = ei[E + e]; }
    int p = atomicAdd(&g_cnt[dst], 1);
    if (p < CAP) g_elist[(size_t)dst * CAP + p] = src;
}

// ---------------------------------------------------------------------------
// K2: layer-1 aggregation (gather) -> bf16 hi/lo in fragment-permuted layout
// warp per node, one float4 per lane (k = 4*lane .. 4*lane+3)
// ---------------------------------------------------------------------------
__global__ void __launch_bounds__(256) k_agg1(const float* __restrict__ x,
                                              const float* __restrict__ eps1p,
                                              int nNodes) {
    int warp = (blockIdx.x * blockDim.x + threadIdx.x) >> 5;
    int lane = threadIdx.x & 31;
    if (warp >= nNodes) return;
    const float4* __restrict__ xv = (const float4*)x;
    float s1 = 1.0f + *eps1p;
    float4 a = xv[(size_t)warp * 32 + lane];
    float4 acc;
    acc.x = s1 * a.x; acc.y = s1 * a.y; acc.z = s1 * a.z; acc.w = s1 * a.w;

    int deg = g_cnt[warp]; if (deg > CAP) deg = CAP;
    const int* __restrict__ lst = &g_elist[(size_t)warp * CAP];
    int e = 0;
    for (; e + 4 <= deg; e += 4) {
        int i0 = lst[e], i1 = lst[e + 1], i2 = lst[e + 2], i3 = lst[e + 3];
        float4 v0 = xv[(size_t)i0 * 32 + lane];
        float4 v1 = xv[(size_t)i1 * 32 + lane];
        float4 v2 = xv[(size_t)i2 * 32 + lane];
        float4 v3 = xv[(size_t)i3 * 32 + lane];
        acc.x += v0.x + v1.x + v2.x + v3.x;
        acc.y += v0.y + v1.y + v2.y + v3.y;
        acc.z += v0.z + v1.z + v2.z + v3.z;
        acc.w += v0.w + v1.w + v2.w + v3.w;
    }
    for (; e < deg; e++) {
        float4 v = xv[(size_t)lst[e] * 32 + lane];
        acc.x += v.x; acc.y += v.y; acc.z += v.z; acc.w += v.w;
    }
    // split fp32 -> bf16 hi + bf16 lo residual
    __nv_bfloat16 hx = __float2bfloat16_rn(acc.x), hy = __float2bfloat16_rn(acc.y);
    __nv_bfloat16 hz = __float2bfloat16_rn(acc.z), hw = __float2bfloat16_rn(acc.w);
    float lx = acc.x - __bfloat162float(hx), ly = acc.y - __bfloat162float(hy);
    float lz = acc.z - __bfloat162float(hz), lw = acc.w - __bfloat162float(hw);
    unsigned h0 = ((unsigned)__bfloat16_as_ushort(hy) << 16) | __bfloat16_as_ushort(hx);
    unsigned h1 = ((unsigned)__bfloat16_as_ushort(hw) << 16) | __bfloat16_as_ushort(hz);
    unsigned l0 = pack_bf16(lx, ly);
    unsigned l1 = pack_bf16(lz, lw);
    // permuted positions: orig word w -> pos = (w<4) ? 2w : 2(w-4)+1
    int kg = lane >> 2;           // 16-k group
    int w0 = 2 * (lane & 3);      // orig word within group (even), w1 = w0+1
    int p0 = (w0 < 4) ? (2 * w0) : (2 * (w0 - 4) + 1);
    int w1 = w0 + 1;
    int p1 = (w1 < 4) ? (2 * w1) : (2 * (w1 - 4) + 1);
    size_t base = (size_t)warp * 64 + kg * 8;
    g_uhi[base + p0] = h0; g_uhi[base + p1] = h1;
    g_ulo[base + p0] = l0; g_ulo[base + p1] = l1;
}

// ---------------------------------------------------------------------------
// K_prep: W1 [k][n] -> Bhi/Blo [n][k] bf16, fragment-permuted.
// Thread per (n, kg, tc): writes uint2 = {word(k=kg*16+tc*2), word(k=...+8)}
// ---------------------------------------------------------------------------
__global__ void k_prep(const float* __restrict__ W1) {
    int L = blockIdx.x * blockDim.x + threadIdx.x;
    if (L >= 256 * 8 * 4) return;
    int n  = L >> 5;
    int kg = (L >> 2) & 7;
    int tc = L & 3;
    int k0 = kg * 16 + tc * 2;
    int k2 = k0 + 8;
    float w00 = W1[(size_t)k0 * 256 + n];
    float w01 = W1[(size_t)(k0 + 1) * 256 + n];
    float w20v = W1[(size_t)k2 * 256 + n];
    float w21v = W1[(size_t)(k2 + 1) * 256 + n];
    __nv_bfloat16 h00 = __float2bfloat16_rn(w00), h01 = __float2bfloat16_rn(w01);
    __nv_bfloat16 h20 = __float2bfloat16_rn(w20v), h21 = __float2bfloat16_rn(w21v);
    unsigned hiA = ((unsigned)__bfloat16_as_ushort(h01) << 16) | __bfloat16_as_ushort(h00);
    unsigned hiB = ((unsigned)__bfloat16_as_ushort(h21) << 16) | __bfloat16_as_ushort(h20);
    unsigned loA = pack_bf16(w00 - __bfloat162float(h00), w01 - __bfloat162float(h01));
    unsigned loB = pack_bf16(w20v - __bfloat162float(h20), w21v - __bfloat162float(h21));
    int u2 = n * 32 + kg * 4 + tc;
    ((uint2*)g_Bhi)[u2] = make_uint2(hiA, hiB);
    ((uint2*)g_Blo)[u2] = make_uint2(loA, loB);
}

// ---------------------------------------------------------------------------
// K3: HMMA GEMM: BM=128, BN=256, K_eff=384 (bf16 split), 512 threads.
// 16 warps: warpM = wid&3 (32 rows each), warpN = wid>>2 (64 cols each).
// Per warp per k16-step: 2 m-tiles x 8 n-tiles mma.m16n8k16.
// Epilogue: bias+ReLU, project onto W2, deterministic reduce -> g_y.
// ---------------------------------------------------------------------------
__global__ void __launch_bounds__(512, 1) k_gemm_mma(
    const float* __restrict__ b1, const float* __restrict__ W2, int nNodes) {

    __shared__ float b1s[256], w20s[256], w21s[256];
    __shared__ float red[128][4][2];

    int t = threadIdx.x;
    int wid = t >> 5, lane = t & 31;
    int g = lane >> 2, tc = lane & 3;
    int warpM = wid & 3, warpN = wid >> 2;
    int rowBase = blockIdx.x * 128;

    for (int i = t; i < 256; i += 512) {
        b1s[i]  = b1[i];
        w20s[i] = W2[2 * i];
        w21s[i] = W2[2 * i + 1];
    }
    __syncthreads();

    // clamped fragment rows (OOB rows computed but discarded at store)
    int r0[2], r1[2];
    #pragma unroll
    for (int mt = 0; mt < 2; mt++) {
        int rr = rowBase + warpM * 32 + mt * 16 + g;
        r0[mt] = (rr < nNodes) ? rr : (nNodes - 1);
        int rr8 = rr + 8;
        r1[mt] = (rr8 < nNodes) ? rr8 : (nNodes - 1);
    }

    float acc[2][8][4];
    #pragma unroll
    for (int mt = 0; mt < 2; mt++)
        #pragma unroll
        for (int nt = 0; nt < 8; nt++)
            #pragma unroll
            for (int j = 0; j < 4; j++) acc[mt][nt][j] = 0.f;

    const uint2* __restrict__ Ahi = (const uint2*)g_uhi;
    const uint2* __restrict__ Alo = (const uint2*)g_ulo;
    const uint2* __restrict__ Bhi = (const uint2*)g_Bhi;
    const uint2* __restrict__ Blo = (const uint2*)g_Blo;

    #pragma unroll 4
    for (int ks = 0; ks < 24; ks++) {
        int s  = ks >> 3;          // 0: uhi*Whi, 1: ulo*Whi, 2: uhi*Wlo
        int kg = ks & 7;
        const uint2* __restrict__ Ap = (s == 1) ? Alo : Ahi;
        const uint2* __restrict__ Bp = (s == 2) ? Blo : Bhi;
        int koff = kg * 4 + tc;

        uint2 bf[8];
        #pragma unroll
        for (int nt = 0; nt < 8; nt++) {
            int n = warpN * 64 + nt * 8 + g;
            bf[nt] = Bp[n * 32 + koff];
        }
        #pragma unroll
        for (int mt = 0; mt < 2; mt++) {
            uint2 aA = Ap[(size_t)r0[mt] * 32 + koff];   // {a0, a2}
            uint2 aB = Ap[(size_t)r1[mt] * 32 + koff];   // {a1, a3}
            #pragma unroll
            for (int nt = 0; nt < 8; nt++) {
                asm volatile(
                    "mma.sync.aligned.m16n8k16.row.col.f32.bf16.bf16.f32 "
                    "{%0,%1,%2,%3}, {%4,%5,%6,%7}, {%8,%9}, {%0,%1,%2,%3};"
                    : "+f"(acc[mt][nt][0]), "+f"(acc[mt][nt][1]),
                      "+f"(acc[mt][nt][2]), "+f"(acc[mt][nt][3])
                    : "r"(aA.x), "r"(aB.x), "r"(aA.y), "r"(aB.y),
                      "r"(bf[nt].x), "r"(bf[nt].y));
            }
        }
    }

    // Epilogue: relu(acc + b1) -> project onto W2; accumulate per-row partials
    float yv[2][2][2];   // [mt][half(row g / g+8)][component]
    #pragma unroll
    for (int mt = 0; mt < 2; mt++)
        #pragma unroll
        for (int h = 0; h < 2; h++) { yv[mt][h][0] = 0.f; yv[mt][h][1] = 0.f; }

    #pragma unroll
    for (int mt = 0; mt < 2; mt++) {
        #pragma unroll
        for (int nt = 0; nt < 8; nt++) {
            int n0 = warpN * 64 + nt * 8 + tc * 2;
            int n1 = n0 + 1;
            float v0 = fmaxf(acc[mt][nt][0] + b1s[n0], 0.f);
            float v1 = fmaxf(acc[mt][nt][1] + b1s[n1], 0.f);
            float v2 = fmaxf(acc[mt][nt][2] + b1s[n0], 0.f);
            float v3 = fmaxf(acc[mt][nt][3] + b1s[n1], 0.f);
            yv[mt][0][0] += v0 * w20s[n0] + v1 * w20s[n1];
            yv[mt][0][1] += v0 * w21s[n0] + v1 * w21s[n1];
            yv[mt][1][0] += v2 * w20s[n0] + v3 * w20s[n1];
            yv[mt][1][1] += v2 * w21s[n0] + v3 * w21s[n1];
        }
    }
    // reduce across the 4 col-threads (same rows): lanes differing in bits 0,1
    #pragma unroll
    for (int mt = 0; mt < 2; mt++)
        #pragma unroll
        for (int h = 0; h < 2; h++)
            #pragma unroll
            for (int c = 0; c < 2; c++) {
                float v = yv[mt][h][c];
                v += __shfl_xor_sync(0xffffffffu, v, 1);
                v += __shfl_xor_sync(0xffffffffu, v, 2);
                yv[mt][h][c] = v;
            }
    if (tc == 0) {
        #pragma unroll
        for (int mt = 0; mt < 2; mt++)
            #pragma unroll
            for (int h = 0; h < 2; h++) {
                int lrow = warpM * 32 + mt * 16 + h * 8 + g;
                red[lrow][warpN][0] = yv[mt][h][0];
                red[lrow][warpN][1] = yv[mt][h][1];
            }
    }
    __syncthreads();
    if (t < 128) {
        int row = rowBase + t;
        if (row < nNodes) {
            float y0 = (red[t][0][0] + red[t][1][0]) + (red[t][2][0] + red[t][3][0]);
            float y1 = (red[t][0][1] + red[t][1][1]) + (red[t][2][1] + red[t][3][1]);
            g_y[2 * row]     = y0;
            g_y[2 * row + 1] = y1;
        }
    }
}

// ---------------------------------------------------------------------------
// K4: layer-2: out[n] = (1+eps2)*y[n] + b2 + sum_{src->n} y[src]
// ---------------------------------------------------------------------------
__global__ void __launch_bounds__(256) k_agg2(const float* __restrict__ b2,
                                              const float* __restrict__ eps2p,
                                              float* __restrict__ outp,
                                              int nNodes) {
    int n = blockIdx.x * blockDim.x + threadIdx.x;
    if (n >= nNodes) return;
    int deg = g_cnt[n]; if (deg > CAP) deg = CAP;
    const int* __restrict__ lst = &g_elist[(size_t)n * CAP];
    const float2* __restrict__ yv = (const float2*)g_y;
    float a0 = 0.f, a1 = 0.f;
    int e = 0;
    for (; e + 4 <= deg; e += 4) {
        int i0 = lst[e], i1 = lst[e + 1], i2 = lst[e + 2], i3 = lst[e + 3];
        float2 v0 = yv[i0], v1 = yv[i1], v2 = yv[i2], v3 = yv[i3];
        a0 += v0.x + v1.x + v2.x + v3.x;
        a1 += v0.y + v1.y + v2.y + v3.y;
    }
    for (; e < deg; e++) {
        float2 v = yv[lst[e]];
        a0 += v.x; a1 += v.y;
    }
    float e2 = 1.0f + *eps2p;
    float2 yn = yv[n];
    float2 res;
    res.x = fmaf(e2, yn.x, b2[0]) + a0;
    res.y = fmaf(e2, yn.y, b2[1]) + a1;
    ((float2*)outp)[n] = res;
}

// ---------------------------------------------------------------------------
extern "C" void kernel_launch(void* const* d_in, const int* in_sizes, int n_in,
                              void* d_out, int out_size) {
    const float* x     = (const float*)d_in[0];
    const int*   ei    = (const int*)d_in[1];
    const float* W1    = (const float*)d_in[2];
    const float* b1    = (const float*)d_in[3];
    const float* W2    = (const float*)d_in[4];
    const float* b2    = (const float*)d_in[5];
    const float* eps1p = (const float*)d_in[6];
    const float* eps2p = (const float*)d_in[7];
    float* outp = (float*)d_out;

    int nNodes = in_sizes[0] / IND;          // 50000
    int E      = in_sizes[1] / 2;            // 800000 edges

    k_init<<<(nNodes + 255) / 256, 256>>>(ei, nNodes);
    k_prep<<<(256 * 8 * 4 + 255) / 256, 256>>>(W1);
    k_build<<<(E + 255) / 256, 256>>>(ei, E);
    k_agg1<<<(nNodes + 7) / 8, 256>>>(x, eps1p, nNodes);
    k_gemm_mma<<<(nNodes + 127) / 128, 512>>>(b1, W2, nNodes);
    k_agg2<<<(nNodes + 255) / 256, 256>>>(b2, eps2p, outp, nNodes);
}